// round 15
// baseline (speedup 1.0000x reference)
#include <cuda_runtime.h>
#include <cuda_fp16.h>
#include <math.h>
#include <stdint.h>

// Problem constants
#define Bb 8
#define Ss 1024
#define Dd 1024
#define Hh 8
#define DKk 128
#define FFf 4096
#define Ll 2

// ---------------- scratch (device globals; no allocation allowed) ----------
__device__ float  g_x [Bb*Ss*Dd];                 // fp32 activation (residual)
__device__ __half g_t2h[Bb*Ss*Dd];                // fp16 branch output
__device__ __half g_xh [Bb*Ss*Dd];
__device__ __half g_yh [Bb*Ss*Dd];
__device__ __half g_kh [Bb*Ss*Dd];
__device__ __half g_vh [Bb*Ss*Dd];                // V row-major [b,s,h*dk]
__device__ __half g_t1h[Bb*Ss*Dd];
__device__ __half g_ffh[Bb*Ss*FFf];
// fp16 weights (converted per layer)
__device__ __half g_wk[Dd*Dd];
__device__ __half g_wv[Dd*Dd];
__device__ __half g_wo[Dd*Dd];
__device__ __half g_w1[FFf*Dd];
__device__ __half g_w2[Dd*FFf];

// ======================= helpers ============================================
__device__ __forceinline__ uint32_t smem_u32(const void* p) {
    uint32_t a;
    asm("{ .reg .u64 t; cvta.to.shared.u64 t, %1; cvt.u32.u64 %0, t; }"
        : "=r"(a) : "l"(p));
    return a;
}

__device__ __forceinline__ void ldsm4(uint32_t* r, uint32_t addr) {
    asm volatile("ldmatrix.sync.aligned.m8n8.x4.shared.b16 {%0,%1,%2,%3}, [%4];"
        : "=r"(r[0]), "=r"(r[1]), "=r"(r[2]), "=r"(r[3]) : "r"(addr));
}

__device__ __forceinline__ void ldsm4t(uint32_t* r, uint32_t addr) {
    asm volatile("ldmatrix.sync.aligned.m8n8.x4.trans.shared.b16 {%0,%1,%2,%3}, [%4];"
        : "=r"(r[0]), "=r"(r[1]), "=r"(r[2]), "=r"(r[3]) : "r"(addr));
}

__device__ __forceinline__ void mma16816(float* c, const uint32_t* a,
                                         const uint32_t* b) {
    asm volatile(
        "mma.sync.aligned.m16n8k16.row.col.f32.f16.f16.f32 "
        "{%0,%1,%2,%3}, {%4,%5,%6,%7}, {%8,%9}, {%0,%1,%2,%3};"
        : "+f"(c[0]), "+f"(c[1]), "+f"(c[2]), "+f"(c[3])
        : "r"(a[0]), "r"(a[1]), "r"(a[2]), "r"(a[3]), "r"(b[0]), "r"(b[1]));
}

__device__ __forceinline__ void cp16(uint32_t dst, const void* src) {
    asm volatile("cp.async.cg.shared.global [%0], [%1], 16;"
        :: "r"(dst), "l"(src));
}
#define CP_COMMIT() asm volatile("cp.async.commit_group;" ::: "memory")
#define CP_WAIT(n)  asm volatile("cp.async.wait_group %0;" :: "n"(n) : "memory")

__device__ __forceinline__ uint32_t h2u(float a, float b) {
    __half2 h = __floats2half2_rn(a, b);
    return *(uint32_t*)&h;
}

// ---------------- small elementwise kernels ---------------------------------
__global__ void add_pos_kernel(const float* __restrict__ q,
                               const float* __restrict__ qa,
                               const float* __restrict__ pe,
                               float* __restrict__ x,
                               __half* __restrict__ xh,
                               __half* __restrict__ yh)
{
    int idx = blockIdx.x * 256 + threadIdx.x;
    int sd  = idx & (Ss*Dd - 1);
    float p = pe[sd];
    float xv = q[idx] + p;
    x[idx]  = xv;
    xh[idx] = __float2half(xv);
    yh[idx] = __float2half(qa[idx] + p);
}

// Convert all 5 weight matrices of one layer in a single launch.
#define NW1 (Dd*Dd)
#define NWF (FFf*Dd)
__global__ void wconv_all(const float* __restrict__ Wk,
                          const float* __restrict__ Wv,
                          const float* __restrict__ Wo,
                          const float* __restrict__ W1,
                          const float* __restrict__ W2,
                          __half* __restrict__ wk, __half* __restrict__ wv,
                          __half* __restrict__ wo, __half* __restrict__ w1,
                          __half* __restrict__ w2)
{
    int i = blockIdx.x * 256 + threadIdx.x;
    if (i < NW1)              wk[i] = __float2half(Wk[i]);
    else if (i < 2*NW1)       wv[i - NW1]   = __float2half(Wv[i - NW1]);
    else if (i < 3*NW1)       wo[i - 2*NW1] = __float2half(Wo[i - 2*NW1]);
    else if (i < 3*NW1 + NWF) w1[i - 3*NW1] = __float2half(W1[i - 3*NW1]);
    else                      w2[i - 3*NW1 - NWF] = __float2half(W2[i - 3*NW1 - NWF]);
}
#define WCONV_TOTAL (3*NW1 + 2*NWF)

// ============ fp16 GEMM: C = A * B^T (+bias)(+relu) =========================
// A: [M,K] fp16 row-major. B: [N,K] fp16 row-major. fp32 accumulate.
// CTA tile 128x128 (8 warps of 32x64), K staged 64 wide, 3-stage cp.async ring,
// one __syncthreads per stage, 2 CTAs/SM.
// blockIdx.z == 1 selects the (A2, B2, bias2, C2) operand set (fused K+V).
#define ROWB 144                    // 64 halves (128B) + 16B pad
#define ATILEB (128 * ROWB)         // 18432
#define BTILEB (128 * ROWB)         // 18432
#define STAGEB (ATILEB + BTILEB)    // 36864
#define NSTAGE 3
#define DSMEM_BYTES (NSTAGE * STAGEB)   // 110592

__device__ __forceinline__ void load_stage(
    int tid, uint32_t base,
    const __half* A, int lda, const __half* B, int ldb,
    int m0, int n0, int k0)
{
#pragma unroll
    for (int j = 0; j < 4; j++) {
        int c = tid + j * 256;              // 0..1023
        int row = c >> 3, c8 = c & 7;
        cp16(base + (uint32_t)(row * ROWB + c8 * 16),
             A + (long)(m0 + row) * lda + k0 + c8 * 8);
    }
#pragma unroll
    for (int j = 0; j < 4; j++) {
        int c = tid + j * 256;
        int row = c >> 3, c8 = c & 7;
        cp16(base + ATILEB + (uint32_t)(row * ROWB + c8 * 16),
             B + (long)(n0 + row) * ldb + k0 + c8 * 8);
    }
}

__global__ void __launch_bounds__(256, 2)
gemm_h(const __half* __restrict__ A, const __half* __restrict__ A2, int lda,
       const __half* __restrict__ B, const __half* __restrict__ B2, int ldb,
       const float* __restrict__ bias, const float* __restrict__ bias2,
       __half* __restrict__ Ch, __half* __restrict__ C2,
       int ldc, int K, int relu)
{
    extern __shared__ char dsm[];
    uint32_t sb = smem_u32(dsm);

    if (blockIdx.z) { A = A2; B = B2; bias = bias2; Ch = C2; }

    const int m0 = blockIdx.y * 128, n0 = blockIdx.x * 128;
    const int tid  = threadIdx.x;
    const int lane = tid & 31, wid = tid >> 5;
    const int mW = (wid & 3) * 32, nW = (wid >> 2) * 64;

    const uint32_t aRowOff = (uint32_t)((mW + (lane & 15)) * ROWB + (lane >> 4) * 16);
    const uint32_t bRowOff = (uint32_t)((nW + (lane & 7) + ((lane >> 4) * 8)) * ROWB
                                        + ((lane >> 3) & 1) * 16);

    const int nst = K >> 6;
    float acc[2][8][4] = {};

    load_stage(tid, sb, A, lda, B, ldb, m0, n0, 0);
    CP_COMMIT();
    if (nst > 1) load_stage(tid, sb + STAGEB, A, lda, B, ldb, m0, n0, 64);
    CP_COMMIT();

    int slot = 0;
    for (int s = 0; s < nst; s++) {
        CP_WAIT(1);
        __syncthreads();            // single barrier per stage
        uint32_t cur = sb + (uint32_t)slot * STAGEB;

        if (s + 2 < nst) {
            int nslot = slot + 2; if (nslot >= NSTAGE) nslot -= NSTAGE;
            load_stage(tid, sb + (uint32_t)nslot * STAGEB,
                       A, lda, B, ldb, m0, n0, (s + 2) * 64);
        }
        CP_COMMIT();

#pragma unroll
        for (int kk = 0; kk < 4; kk++) {
            const uint32_t kb = (uint32_t)kk * 32;
            uint32_t a[2][4], b[4][4];
#pragma unroll
            for (int mt = 0; mt < 2; mt++)
                ldsm4(a[mt], cur + aRowOff + mt * (16 * ROWB) + kb);
#pragma unroll
            for (int nh = 0; nh < 4; nh++)
                ldsm4(b[nh], cur + ATILEB + bRowOff + nh * (16 * ROWB) + kb);
#pragma unroll
            for (int nh = 0; nh < 4; nh++)
#pragma unroll
                for (int hf = 0; hf < 2; hf++)
#pragma unroll
                    for (int mt = 0; mt < 2; mt++)
                        mma16816(acc[mt][nh*2+hf], a[mt], b[nh] + 2*hf);
        }
        slot++; if (slot == NSTAGE) slot = 0;
    }

    // ---- epilogue: fp16 output ----
    const int rIn = lane >> 2, cIn = (lane & 3) * 2;
#pragma unroll
    for (int mt = 0; mt < 2; mt++) {
#pragma unroll
        for (int nt = 0; nt < 8; nt++) {
            float* a4 = acc[mt][nt];
            int col = n0 + nW + nt*8 + cIn;
            long r0 = (long)m0 + mW + mt*16 + rIn;
            long r1 = r0 + 8;
            float v0 = a4[0], v1 = a4[1], v2 = a4[2], v3 = a4[3];
            if (bias) {
                float b0_ = bias[col], b1_ = bias[col+1];
                v0 += b0_; v1 += b1_; v2 += b0_; v3 += b1_;
            }
            if (relu) {
                v0 = fmaxf(v0,0.f); v1 = fmaxf(v1,0.f);
                v2 = fmaxf(v2,0.f); v3 = fmaxf(v3,0.f);
            }
            *(__half2*)(Ch + r0*ldc + col) = __floats2half2_rn(v0, v1);
            *(__half2*)(Ch + r1*ldc + col) = __floats2half2_rn(v2, v3);
        }
    }
}

// ============ fused flash attention (strict causal, row0 zeroed) ============
// 128-row K/V blocks, 2-deep cp.async prefetch, heavy-first ordering.
// Diagonal block: warp w only computes tiles p <= w (rest fully masked);
// softmax in exp2 form with 1/sqrt(dk)*log2(e) folded into one fma.
#define FROWB 272
#define FTILE (128 * FROWB)                 // 34816
#define FL_SMEM (5 * FTILE)                 // Q + 2xK + 2xV = 174080

__device__ __forceinline__ void fl_load(int tid, uint32_t dstK, uint32_t dstV,
                                        const __half* Kb, const __half* Vb,
                                        int s0)
{
#pragma unroll
    for (int j = 0; j < 8; j++) {
        int c = tid + j * 256;              // 0..2047
        int row = c >> 4, cc = c & 15;
        uint32_t off = (uint32_t)(row * FROWB + cc * 16);
        cp16(dstK + off, Kb + (long)(s0 + row) * Dd + cc * 8);
        cp16(dstV + off, Vb + (long)(s0 + row) * Dd + cc * 8);
    }
}

__global__ void __launch_bounds__(256, 1)
flash_attn(const __half* __restrict__ kh, const __half* __restrict__ vh,
           __half* __restrict__ t1h)
{
    extern __shared__ char dsm[];
    uint32_t sb = smem_u32(dsm);
    uint32_t sQ = sb, sK = sb + FTILE, sV = sb + 3 * FTILE;

    // heavy-first: largest q0 (most K blocks) scheduled earliest
    const int q0 = (int)(gridDim.x - 1 - blockIdx.x) * 128;
    const int bh = blockIdx.y;
    const int b = bh >> 3, h = bh & 7;
    const __half* Kbase = kh + ((long)b * Ss) * Dd + h * DKk;
    const __half* Vbase = vh + ((long)b * Ss) * Dd + h * DKk;

    const int tid = threadIdx.x, lane = tid & 31, w = tid >> 5;
    const float Cs = 0.08838834764831845f * 1.44269504088896f; // isd*log2(e)

#pragma unroll
    for (int j = 0; j < 8; j++) {
        int c = tid + j * 256;
        int row = c >> 4, cc = c & 15;
        cp16(sQ + (uint32_t)(row * FROWB + cc * 16),
             Kbase + (long)(q0 + row) * Dd + cc * 8);
    }
    CP_COMMIT();
    fl_load(tid, sK, sV, Kbase, Vbase, 0);
    CP_COMMIT();

    CP_WAIT(1);          // Q ready
    __syncthreads();

    uint32_t qf[8][4];
    const uint32_t qAddr = sQ + (uint32_t)((w * 16 + (lane & 15)) * FROWB
                                           + (lane >> 4) * 16);
#pragma unroll
    for (int kk = 0; kk < 8; kk++) ldsm4(qf[kk], qAddr + kk * 32);

    float o[16][4] = {};
    float mS[2] = {-1e30f, -1e30f};     // running max, raw score units
    float lS[2] = {0.f, 0.f};

    const uint32_t bOff = (uint32_t)(((lane & 7) + ((lane >> 4) * 8)) * FROWB
                                     + ((lane >> 3) & 1) * 16);
    const uint32_t vOff = (uint32_t)((lane & 15) * FROWB + (lane >> 4) * 16);
    const int nkb = q0 / 128 + 1;

    for (int kb = 0; kb < nkb; kb++) {
        if (kb + 1 < nkb)
            fl_load(tid, sK + (uint32_t)((kb + 1) & 1) * FTILE,
                    sV + (uint32_t)((kb + 1) & 1) * FTILE,
                    Kbase, Vbase, (kb + 1) * 128);
        CP_COMMIT();
        CP_WAIT(1);
        __syncthreads();
        uint32_t curK = sK + (uint32_t)(kb & 1) * FTILE;
        uint32_t curV = sV + (uint32_t)(kb & 1) * FTILE;

        const bool diag = (kb == nkb - 1);
        const int pb = diag ? (w + 1) : 8;      // tile bound (uniform per warp)

        // ---- S = Q @ Kblk^T  (raw, unscaled) ----
        float s[16][4] = {};
#pragma unroll
        for (int kk = 0; kk < 8; kk++) {
            uint32_t bf[8][4];
#pragma unroll
            for (int p = 0; p < 8; p++)
                if (p < pb)
                    ldsm4(bf[p], curK + bOff + p * (16 * FROWB) + kk * 32);
#pragma unroll
            for (int p = 0; p < 8; p++)
                if (p < pb) {
                    mma16816(s[2*p],   qf[kk], bf[p]);
                    mma16816(s[2*p+1], qf[kk], bf[p] + 2);
                }
        }

        // strict causal mask: only tile p == w of the diagonal block crosses
        // the boundary (tiles p < w are fully unmasked, p > w skipped).
        if (diag) {
            int rA = q0 + w * 16 + (lane >> 2);
            int rB = rA + 8;
            int cb = kb * 128 + w * 16 + (lane & 3) * 2;
#pragma unroll
            for (int t = 0; t < 2; t++) {
                int nt = 2*w + t;
                int c0 = cb + t * 8, c1 = c0 + 1;
                if (c0 >= rA) s[nt][0] = -1e30f;
                if (c1 >= rA) s[nt][1] = -1e30f;
                if (c0 >= rB) s[nt][2] = -1e30f;
                if (c1 >= rB) s[nt][3] = -1e30f;
            }
        }

        // ---- online softmax (exp2 with folded scale) ----
        float rAm = -1e30f, rBm = -1e30f;
#pragma unroll
        for (int nt = 0; nt < 16; nt++)
            if (nt < 2 * pb) {
                rAm = fmaxf(rAm, fmaxf(s[nt][0], s[nt][1]));
                rBm = fmaxf(rBm, fmaxf(s[nt][2], s[nt][3]));
            }
        rAm = fmaxf(rAm, __shfl_xor_sync(0xFFFFFFFFu, rAm, 1));
        rAm = fmaxf(rAm, __shfl_xor_sync(0xFFFFFFFFu, rAm, 2));
        rBm = fmaxf(rBm, __shfl_xor_sync(0xFFFFFFFFu, rBm, 1));
        rBm = fmaxf(rBm, __shfl_xor_sync(0xFFFFFFFFu, rBm, 2));

        float mA = fmaxf(mS[0], rAm), mB = fmaxf(mS[1], rBm);
        float aA = exp2f((mS[0] - mA) * Cs), aB = exp2f((mS[1] - mB) * Cs);
        mS[0] = mA; mS[1] = mB;
        float nmAC = -mA * Cs, nmBC = -mB * Cs;

        float sumA = 0.f, sumB = 0.f;
        uint32_t pf[8][4];
#pragma unroll
        for (int j = 0; j < 8; j++)
            if (j < pb) {
                float e0 = exp2f(fmaf(s[2*j][0],   Cs, nmAC));
                float e1 = exp2f(fmaf(s[2*j][1],   Cs, nmAC));
                float e2 = exp2f(fmaf(s[2*j][2],   Cs, nmBC));
                float e3 = exp2f(fmaf(s[2*j][3],   Cs, nmBC));
                float f0 = exp2f(fmaf(s[2*j+1][0], Cs, nmAC));
                float f1 = exp2f(fmaf(s[2*j+1][1], Cs, nmAC));
                float f2 = exp2f(fmaf(s[2*j+1][2], Cs, nmBC));
                float f3 = exp2f(fmaf(s[2*j+1][3], Cs, nmBC));
                sumA += e0 + e1 + f0 + f1;
                sumB += e2 + e3 + f2 + f3;
                pf[j][0] = h2u(e0, e1); pf[j][1] = h2u(e2, e3);
                pf[j][2] = h2u(f0, f1); pf[j][3] = h2u(f2, f3);
            }
        sumA += __shfl_xor_sync(0xFFFFFFFFu, sumA, 1);
        sumA += __shfl_xor_sync(0xFFFFFFFFu, sumA, 2);
        sumB += __shfl_xor_sync(0xFFFFFFFFu, sumB, 1);
        sumB += __shfl_xor_sync(0xFFFFFFFFu, sumB, 2);
        lS[0] = lS[0] * aA + sumA;
        lS[1] = lS[1] * aB + sumB;

#pragma unroll
        for (int nt = 0; nt < 16; nt++) {
            o[nt][0] *= aA; o[nt][1] *= aA; o[nt][2] *= aB; o[nt][3] *= aB;
        }

        // ---- O += P @ Vblk  (V row-major, trans ldsm; j chunks < pb) ----
#pragma unroll
        for (int j = 0; j < 8; j++)
            if (j < pb) {
                uint32_t vf[8][4];
#pragma unroll
                for (int p = 0; p < 8; p++)
                    ldsm4t(vf[p], curV + vOff + j * (16 * FROWB) + p * 32);
#pragma unroll
                for (int p = 0; p < 8; p++) {
                    mma16816(o[2*p],   pf[j], vf[p]);
                    mma16816(o[2*p+1], pf[j], vf[p] + 2);
                }
            }
        if (!diag) __syncthreads();   // protect buffer reuse (not needed last)
    }

    int rowA = q0 + w * 16 + (lane >> 2);
    int rowB = rowA + 8;
    float invA = (rowA == 0) ? 0.f : 1.f / lS[0];
    float invB = 1.f / lS[1];
    __half* oA = t1h + ((long)b * Ss + rowA) * Dd + h * DKk + (lane & 3) * 2;
    __half* oB = t1h + ((long)b * Ss + rowB) * Dd + h * DKk + (lane & 3) * 2;
#pragma unroll
    for (int nt = 0; nt < 16; nt++) {
        *(__half2*)(oA + nt * 8) = __floats2half2_rn(o[nt][0]*invA, o[nt][1]*invA);
        *(__half2*)(oB + nt * 8) = __floats2half2_rn(o[nt][2]*invB, o[nt][3]*invB);
    }
}

// ---------------- residual add + LayerNorm (t input fp16) -------------------
__global__ void ln_res(const float* __restrict__ x, const __half* __restrict__ t,
                       const float* __restrict__ g, const float* __restrict__ b,
                       float* __restrict__ out, __half* __restrict__ outh)
{
    __shared__ float red[256];
    long row = blockIdx.x;
    int tid = threadIdx.x;
    const float*  xp = x + row * Dd;
    const __half* tp = t + row * Dd;

    float v[4];
    float s = 0.f;
#pragma unroll
    for (int q = 0; q < 4; q++) {
        int c = tid + q * 256;
        v[q] = xp[c] + __half2float(tp[c]);
        s += v[q];
    }
    red[tid] = s; __syncthreads();
    for (int off = 128; off > 0; off >>= 1) {
        if (tid < off) red[tid] += red[tid + off];
        __syncthreads();
    }
    float mean = red[0] * (1.f / Dd);
    __syncthreads();

    float s2 = 0.f;
#pragma unroll
    for (int q = 0; q < 4; q++) {
        float d = v[q] - mean;
        s2 += d * d;
    }
    red[tid] = s2; __syncthreads();
    for (int off = 128; off > 0; off >>= 1) {
        if (tid < off) red[tid] += red[tid + off];
        __syncthreads();
    }
    float inv = rsqrtf(red[0] * (1.f / Dd) + 1e-5f);

#pragma unroll
    for (int q = 0; q < 4; q++) {
        int c = tid + q * 256;
        float val = (v[q] - mean) * inv * g[c] + b[c];
        out[row * Dd + c] = val;
        if (outh) outh[row * Dd + c] = __float2half(val);
    }
}

// ---------------- driver ----------------------------------------------------
extern "C" void kernel_launch(void* const* d_in, const int* in_sizes, int n_in,
                              void* d_out, int out_size)
{
    const float* q_embed = (const float*)d_in[0];
    const float* qa_embed= (const float*)d_in[1];
    const float* pos     = (const float*)d_in[2];
    const float* Wk  = (const float*)d_in[3];
    const float* bk  = (const float*)d_in[4];
    const float* Wv  = (const float*)d_in[5];
    const float* bv  = (const float*)d_in[6];
    const float* Wo  = (const float*)d_in[7];
    const float* bo  = (const float*)d_in[8];
    const float* ln1g= (const float*)d_in[9];
    const float* ln1b= (const float*)d_in[10];
    const float* W1  = (const float*)d_in[11];
    const float* b1  = (const float*)d_in[12];
    const float* W2  = (const float*)d_in[13];
    const float* b2  = (const float*)d_in[14];
    const float* ln2g= (const float*)d_in[15];
    const float* ln2b= (const float*)d_in[16];
    float* out = (float*)d_out;

    float *x;
    __half *t2h, *xh, *yh, *kh, *vh, *t1h, *ffh;
    __half *wk, *wv, *wo, *w1, *w2;
    cudaGetSymbolAddress((void**)&x,   g_x);
    cudaGetSymbolAddress((void**)&t2h, g_t2h);
    cudaGetSymbolAddress((void**)&xh,  g_xh);
    cudaGetSymbolAddress((void**)&yh,  g_yh);
    cudaGetSymbolAddress((void**)&kh,  g_kh);
    cudaGetSymbolAddress((void**)&vh,  g_vh);
    cudaGetSymbolAddress((void**)&t1h, g_t1h);
    cudaGetSymbolAddress((void**)&ffh, g_ffh);
    cudaGetSymbolAddress((void**)&wk,  g_wk);
    cudaGetSymbolAddress((void**)&wv,  g_wv);
    cudaGetSymbolAddress((void**)&wo,  g_wo);
    cudaGetSymbolAddress((void**)&w1,  g_w1);
    cudaGetSymbolAddress((void**)&w2,  g_w2);

    cudaFuncSetAttribute(gemm_h, cudaFuncAttributeMaxDynamicSharedMemorySize,
                         DSMEM_BYTES);
    cudaFuncSetAttribute(flash_attn, cudaFuncAttributeMaxDynamicSharedMemorySize,
                         FL_SMEM);

    add_pos_kernel<<<(Bb*Ss*Dd)/256, 256>>>(q_embed, qa_embed, pos, x, xh, yh);

    for (int l = 0; l < Ll; l++) {
        const float* bkl_ = bk + (long)l*Dd;
        const float* bvl_ = bv + (long)l*Dd;
        const float* bol_ = bo + (long)l*Dd;
        const float* b1l_ = b1 + (long)l*FFf;
        const float* b2l_ = b2 + (long)l*Dd;

        wconv_all<<<(WCONV_TOTAL + 255)/256, 256>>>(
            Wk + (long)l*Dd*Dd, Wv + (long)l*Dd*Dd, Wo + (long)l*Dd*Dd,
            W1 + (long)l*FFf*Dd, W2 + (long)l*Dd*FFf,
            wk, wv, wo, w1, w2);

        dim3 gKV(Dd/128,  (Bb*Ss)/128, 2);  // fused K+V projections
        dim3 gP (Dd/128,  (Bb*Ss)/128, 1);
        dim3 gF1(FFf/128, (Bb*Ss)/128, 1);
        dim3 gF2(Dd/128,  (Bb*Ss)/128, 1);
        dim3 gFA(Ss/128,  Bb*Hh);

        // K = x @ Wk^T + bk ; V = y @ Wv^T + bv   (one fused launch, z=0/1)
        gemm_h<<<gKV, 256, DSMEM_BYTES>>>(xh, yh, Dd, wk, wv, Dd,
                                          bkl_, bvl_, kh, vh, Dd, Dd, 0);
        // fused attention: scores + masked softmax + P@V -> t1h
        flash_attn<<<gFA, 256, FL_SMEM>>>(kh, vh, t1h);
        // t2 = t1 @ Wo^T + bo -> fp16
        gemm_h<<<gP, 256, DSMEM_BYTES>>>(t1h, nullptr, Dd, wo, nullptr, Dd,
                                         bol_, nullptr, t2h, nullptr, Dd, Dd, 0);
        // x = LN(x + t2) -> fp32 + fp16
        ln_res<<<Bb*Ss, 256>>>(x, t2h, ln1g + (long)l*Dd, ln1b + (long)l*Dd, x, xh);
        // ff = relu(x @ W1^T + b1) -> fp16
        gemm_h<<<gF1, 256, DSMEM_BYTES>>>(xh, nullptr, Dd, w1, nullptr, Dd,
                                          b1l_, nullptr, ffh, nullptr, FFf, Dd, 1);
        // t2 = ff @ W2^T + b2 -> fp16
        gemm_h<<<gF2, 256, DSMEM_BYTES>>>(ffh, nullptr, FFf, w2, nullptr, FFf,
                                          b2l_, nullptr, t2h, nullptr, Dd, FFf, 0);
        // x = LN(x + t2); final layer -> d_out (fp32 only)
        float* xout = (l == Ll - 1) ? out : x;
        __half* xhout = (l == Ll - 1) ? nullptr : xh;
        ln_res<<<Bb*Ss, 256>>>(x, t2h, ln2g + (long)l*Dd, ln2b + (long)l*Dd,
                               xout, xhout);
    }
}

// round 16
// speedup vs baseline: 1.3128x; 1.3128x over previous
#include <cuda_runtime.h>
#include <cuda_fp16.h>
#include <math.h>
#include <stdint.h>

// Problem constants
#define Bb 8
#define Ss 1024
#define Dd 1024
#define Hh 8
#define DKk 128
#define FFf 4096
#define Ll 2

// ---------------- scratch (device globals; no allocation allowed) ----------
__device__ float  g_x [Bb*Ss*Dd];                 // fp32 activation (residual)
__device__ __half g_t2h[Bb*Ss*Dd];                // fp16 branch output
__device__ __half g_xh [Bb*Ss*Dd];
__device__ __half g_yh [Bb*Ss*Dd];
__device__ __half g_kh [Bb*Ss*Dd];
__device__ __half g_vh [Bb*Ss*Dd];                // V row-major [b,s,h*dk]
__device__ __half g_t1h[Bb*Ss*Dd];
__device__ __half g_ffh[Bb*Ss*FFf];
// fp16 weights (converted per layer)
__device__ __half g_wk[Dd*Dd];
__device__ __half g_wv[Dd*Dd];
__device__ __half g_wo[Dd*Dd];
__device__ __half g_w1[FFf*Dd];
__device__ __half g_w2[Dd*FFf];

// ======================= helpers ============================================
__device__ __forceinline__ uint32_t smem_u32(const void* p) {
    uint32_t a;
    asm("{ .reg .u64 t; cvta.to.shared.u64 t, %1; cvt.u32.u64 %0, t; }"
        : "=r"(a) : "l"(p));
    return a;
}

__device__ __forceinline__ void ldsm4(uint32_t* r, uint32_t addr) {
    asm volatile("ldmatrix.sync.aligned.m8n8.x4.shared.b16 {%0,%1,%2,%3}, [%4];"
        : "=r"(r[0]), "=r"(r[1]), "=r"(r[2]), "=r"(r[3]) : "r"(addr));
}

__device__ __forceinline__ void ldsm4t(uint32_t* r, uint32_t addr) {
    asm volatile("ldmatrix.sync.aligned.m8n8.x4.trans.shared.b16 {%0,%1,%2,%3}, [%4];"
        : "=r"(r[0]), "=r"(r[1]), "=r"(r[2]), "=r"(r[3]) : "r"(addr));
}

__device__ __forceinline__ void mma16816(float* c, const uint32_t* a,
                                         const uint32_t* b) {
    asm volatile(
        "mma.sync.aligned.m16n8k16.row.col.f32.f16.f16.f32 "
        "{%0,%1,%2,%3}, {%4,%5,%6,%7}, {%8,%9}, {%0,%1,%2,%3};"
        : "+f"(c[0]), "+f"(c[1]), "+f"(c[2]), "+f"(c[3])
        : "r"(a[0]), "r"(a[1]), "r"(a[2]), "r"(a[3]), "r"(b[0]), "r"(b[1]));
}

__device__ __forceinline__ void cp16(uint32_t dst, const void* src) {
    asm volatile("cp.async.cg.shared.global [%0], [%1], 16;"
        :: "r"(dst), "l"(src));
}
#define CP_COMMIT() asm volatile("cp.async.commit_group;" ::: "memory")
#define CP_WAIT(n)  asm volatile("cp.async.wait_group %0;" :: "n"(n) : "memory")

__device__ __forceinline__ uint32_t h2u(float a, float b) {
    __half2 h = __floats2half2_rn(a, b);
    return *(uint32_t*)&h;
}

// ---------------- small elementwise kernels ---------------------------------
__global__ void add_pos_kernel(const float* __restrict__ q,
                               const float* __restrict__ qa,
                               const float* __restrict__ pe,
                               float* __restrict__ x,
                               __half* __restrict__ xh,
                               __half* __restrict__ yh)
{
    int idx = blockIdx.x * 256 + threadIdx.x;
    int sd  = idx & (Ss*Dd - 1);
    float p = pe[sd];
    float xv = q[idx] + p;
    x[idx]  = xv;
    xh[idx] = __float2half(xv);
    yh[idx] = __float2half(qa[idx] + p);
}

// Convert all 5 weight matrices of one layer in a single launch.
#define NW1 (Dd*Dd)
#define NWF (FFf*Dd)
__global__ void wconv_all(const float* __restrict__ Wk,
                          const float* __restrict__ Wv,
                          const float* __restrict__ Wo,
                          const float* __restrict__ W1,
                          const float* __restrict__ W2,
                          __half* __restrict__ wk, __half* __restrict__ wv,
                          __half* __restrict__ wo, __half* __restrict__ w1,
                          __half* __restrict__ w2)
{
    int i = blockIdx.x * 256 + threadIdx.x;
    if (i < NW1)              wk[i] = __float2half(Wk[i]);
    else if (i < 2*NW1)       wv[i - NW1]   = __float2half(Wv[i - NW1]);
    else if (i < 3*NW1)       wo[i - 2*NW1] = __float2half(Wo[i - 2*NW1]);
    else if (i < 3*NW1 + NWF) w1[i - 3*NW1] = __float2half(W1[i - 3*NW1]);
    else                      w2[i - 3*NW1 - NWF] = __float2half(W2[i - 3*NW1 - NWF]);
}
#define WCONV_TOTAL (3*NW1 + 2*NWF)

// ============ fp16 GEMM: C = A * B^T (+bias)(+relu) =========================
// A: [M,K] fp16 row-major. B: [N,K] fp16 row-major. fp32 accumulate.
// CTA tile 128x128 (8 warps of 32x64), K staged 64 wide, 3-stage cp.async ring,
// one __syncthreads per stage, 2 CTAs/SM.
// blockIdx.z == 1 selects the (A2, B2, bias2, C2) operand set (fused K+V).
#define ROWB 144                    // 64 halves (128B) + 16B pad
#define ATILEB (128 * ROWB)         // 18432
#define BTILEB (128 * ROWB)         // 18432
#define STAGEB (ATILEB + BTILEB)    // 36864
#define NSTAGE 3
#define DSMEM_BYTES (NSTAGE * STAGEB)   // 110592

__device__ __forceinline__ void load_stage(
    int tid, uint32_t base,
    const __half* A, int lda, const __half* B, int ldb,
    int m0, int n0, int k0)
{
#pragma unroll
    for (int j = 0; j < 4; j++) {
        int c = tid + j * 256;              // 0..1023
        int row = c >> 3, c8 = c & 7;
        cp16(base + (uint32_t)(row * ROWB + c8 * 16),
             A + (long)(m0 + row) * lda + k0 + c8 * 8);
    }
#pragma unroll
    for (int j = 0; j < 4; j++) {
        int c = tid + j * 256;
        int row = c >> 3, c8 = c & 7;
        cp16(base + ATILEB + (uint32_t)(row * ROWB + c8 * 16),
             B + (long)(n0 + row) * ldb + k0 + c8 * 8);
    }
}

__global__ void __launch_bounds__(256, 2)
gemm_h(const __half* __restrict__ A, const __half* __restrict__ A2, int lda,
       const __half* __restrict__ B, const __half* __restrict__ B2, int ldb,
       const float* __restrict__ bias, const float* __restrict__ bias2,
       __half* __restrict__ Ch, __half* __restrict__ C2,
       int ldc, int K, int relu)
{
    extern __shared__ char dsm[];
    uint32_t sb = smem_u32(dsm);

    if (blockIdx.z) { A = A2; B = B2; bias = bias2; Ch = C2; }

    const int m0 = blockIdx.y * 128, n0 = blockIdx.x * 128;
    const int tid  = threadIdx.x;
    const int lane = tid & 31, wid = tid >> 5;
    const int mW = (wid & 3) * 32, nW = (wid >> 2) * 64;

    const uint32_t aRowOff = (uint32_t)((mW + (lane & 15)) * ROWB + (lane >> 4) * 16);
    const uint32_t bRowOff = (uint32_t)((nW + (lane & 7) + ((lane >> 4) * 8)) * ROWB
                                        + ((lane >> 3) & 1) * 16);

    const int nst = K >> 6;
    float acc[2][8][4] = {};

    load_stage(tid, sb, A, lda, B, ldb, m0, n0, 0);
    CP_COMMIT();
    if (nst > 1) load_stage(tid, sb + STAGEB, A, lda, B, ldb, m0, n0, 64);
    CP_COMMIT();

    int slot = 0;
    for (int s = 0; s < nst; s++) {
        CP_WAIT(1);
        __syncthreads();            // single barrier per stage
        uint32_t cur = sb + (uint32_t)slot * STAGEB;

        if (s + 2 < nst) {
            int nslot = slot + 2; if (nslot >= NSTAGE) nslot -= NSTAGE;
            load_stage(tid, sb + (uint32_t)nslot * STAGEB,
                       A, lda, B, ldb, m0, n0, (s + 2) * 64);
        }
        CP_COMMIT();

#pragma unroll
        for (int kk = 0; kk < 4; kk++) {
            const uint32_t kb = (uint32_t)kk * 32;
            uint32_t a[2][4], b[4][4];
#pragma unroll
            for (int mt = 0; mt < 2; mt++)
                ldsm4(a[mt], cur + aRowOff + mt * (16 * ROWB) + kb);
#pragma unroll
            for (int nh = 0; nh < 4; nh++)
                ldsm4(b[nh], cur + ATILEB + bRowOff + nh * (16 * ROWB) + kb);
#pragma unroll
            for (int nh = 0; nh < 4; nh++)
#pragma unroll
                for (int hf = 0; hf < 2; hf++)
#pragma unroll
                    for (int mt = 0; mt < 2; mt++)
                        mma16816(acc[mt][nh*2+hf], a[mt], b[nh] + 2*hf);
        }
        slot++; if (slot == NSTAGE) slot = 0;
    }

    // ---- epilogue: fp16 output ----
    const int rIn = lane >> 2, cIn = (lane & 3) * 2;
#pragma unroll
    for (int mt = 0; mt < 2; mt++) {
#pragma unroll
        for (int nt = 0; nt < 8; nt++) {
            float* a4 = acc[mt][nt];
            int col = n0 + nW + nt*8 + cIn;
            long r0 = (long)m0 + mW + mt*16 + rIn;
            long r1 = r0 + 8;
            float v0 = a4[0], v1 = a4[1], v2 = a4[2], v3 = a4[3];
            if (bias) {
                float b0_ = bias[col], b1_ = bias[col+1];
                v0 += b0_; v1 += b1_; v2 += b0_; v3 += b1_;
            }
            if (relu) {
                v0 = fmaxf(v0,0.f); v1 = fmaxf(v1,0.f);
                v2 = fmaxf(v2,0.f); v3 = fmaxf(v3,0.f);
            }
            *(__half2*)(Ch + r0*ldc + col) = __floats2half2_rn(v0, v1);
            *(__half2*)(Ch + r1*ldc + col) = __floats2half2_rn(v2, v3);
        }
    }
}

// ============ fused flash attention (strict causal, row0 zeroed) ============
// R14 control flow exactly (full unrolled tiles, full mask, sync each iter);
// softmax in exp2 form with 1/sqrt(dk)*log2(e) folded into one fma.
#define FROWB 272
#define FTILE (128 * FROWB)                 // 34816
#define FL_SMEM (5 * FTILE)                 // Q + 2xK + 2xV = 174080

__device__ __forceinline__ void fl_load(int tid, uint32_t dstK, uint32_t dstV,
                                        const __half* Kb, const __half* Vb,
                                        int s0)
{
#pragma unroll
    for (int j = 0; j < 8; j++) {
        int c = tid + j * 256;              // 0..2047
        int row = c >> 4, cc = c & 15;
        uint32_t off = (uint32_t)(row * FROWB + cc * 16);
        cp16(dstK + off, Kb + (long)(s0 + row) * Dd + cc * 8);
        cp16(dstV + off, Vb + (long)(s0 + row) * Dd + cc * 8);
    }
}

__global__ void __launch_bounds__(256, 1)
flash_attn(const __half* __restrict__ kh, const __half* __restrict__ vh,
           __half* __restrict__ t1h)
{
    extern __shared__ char dsm[];
    uint32_t sb = smem_u32(dsm);
    uint32_t sQ = sb, sK = sb + FTILE, sV = sb + 3 * FTILE;

    // heavy-first: largest q0 (most K blocks) scheduled earliest
    const int q0 = (int)(gridDim.x - 1 - blockIdx.x) * 128;
    const int bh = blockIdx.y;
    const int b = bh >> 3, h = bh & 7;
    const __half* Kbase = kh + ((long)b * Ss) * Dd + h * DKk;
    const __half* Vbase = vh + ((long)b * Ss) * Dd + h * DKk;

    const int tid = threadIdx.x, lane = tid & 31, w = tid >> 5;
    const float Cs = 0.08838834764831845f * 1.44269504088896f; // isd*log2(e)

#pragma unroll
    for (int j = 0; j < 8; j++) {
        int c = tid + j * 256;
        int row = c >> 4, cc = c & 15;
        cp16(sQ + (uint32_t)(row * FROWB + cc * 16),
             Kbase + (long)(q0 + row) * Dd + cc * 8);
    }
    CP_COMMIT();
    fl_load(tid, sK, sV, Kbase, Vbase, 0);
    CP_COMMIT();

    CP_WAIT(1);          // Q ready
    __syncthreads();

    uint32_t qf[8][4];
    const uint32_t qAddr = sQ + (uint32_t)((w * 16 + (lane & 15)) * FROWB
                                           + (lane >> 4) * 16);
#pragma unroll
    for (int kk = 0; kk < 8; kk++) ldsm4(qf[kk], qAddr + kk * 32);

    float o[16][4] = {};
    float mS[2] = {-1e30f, -1e30f};     // running max, raw score units
    float lS[2] = {0.f, 0.f};

    const uint32_t bOff = (uint32_t)(((lane & 7) + ((lane >> 4) * 8)) * FROWB
                                     + ((lane >> 3) & 1) * 16);
    const uint32_t vOff = (uint32_t)((lane & 15) * FROWB + (lane >> 4) * 16);
    const int nkb = q0 / 128 + 1;

    for (int kb = 0; kb < nkb; kb++) {
        if (kb + 1 < nkb)
            fl_load(tid, sK + (uint32_t)((kb + 1) & 1) * FTILE,
                    sV + (uint32_t)((kb + 1) & 1) * FTILE,
                    Kbase, Vbase, (kb + 1) * 128);
        CP_COMMIT();
        CP_WAIT(1);
        __syncthreads();
        uint32_t curK = sK + (uint32_t)(kb & 1) * FTILE;
        uint32_t curV = sV + (uint32_t)(kb & 1) * FTILE;

        // ---- S = Q @ Kblk^T  (raw, unscaled) ----
        float s[16][4] = {};
#pragma unroll
        for (int kk = 0; kk < 8; kk++) {
            uint32_t bf[8][4];
#pragma unroll
            for (int p = 0; p < 8; p++)
                ldsm4(bf[p], curK + bOff + p * (16 * FROWB) + kk * 32);
#pragma unroll
            for (int p = 0; p < 8; p++) {
                mma16816(s[2*p],   qf[kk], bf[p]);
                mma16816(s[2*p+1], qf[kk], bf[p] + 2);
            }
        }

        // strict causal mask (raw-score units; mask sentinel is -1e30)
        if (kb == nkb - 1) {
            int rA = q0 + w * 16 + (lane >> 2);
            int rB = rA + 8;
            int cb = kb * 128 + (lane & 3) * 2;
#pragma unroll
            for (int nt = 0; nt < 16; nt++) {
                int c0 = cb + nt * 8, c1 = c0 + 1;
                if (c0 >= rA) s[nt][0] = -1e30f;
                if (c1 >= rA) s[nt][1] = -1e30f;
                if (c0 >= rB) s[nt][2] = -1e30f;
                if (c1 >= rB) s[nt][3] = -1e30f;
            }
        }

        // ---- online softmax (exp2 with folded scale) ----
        float rAm = -1e30f, rBm = -1e30f;
#pragma unroll
        for (int nt = 0; nt < 16; nt++) {
            rAm = fmaxf(rAm, fmaxf(s[nt][0], s[nt][1]));
            rBm = fmaxf(rBm, fmaxf(s[nt][2], s[nt][3]));
        }
        rAm = fmaxf(rAm, __shfl_xor_sync(0xFFFFFFFFu, rAm, 1));
        rAm = fmaxf(rAm, __shfl_xor_sync(0xFFFFFFFFu, rAm, 2));
        rBm = fmaxf(rBm, __shfl_xor_sync(0xFFFFFFFFu, rBm, 1));
        rBm = fmaxf(rBm, __shfl_xor_sync(0xFFFFFFFFu, rBm, 2));

        float mA = fmaxf(mS[0], rAm), mB = fmaxf(mS[1], rBm);
        float aA = exp2f((mS[0] - mA) * Cs), aB = exp2f((mS[1] - mB) * Cs);
        mS[0] = mA; mS[1] = mB;
        float nmAC = -mA * Cs, nmBC = -mB * Cs;

        float sumA = 0.f, sumB = 0.f;
        uint32_t pf[8][4];
#pragma unroll
        for (int j = 0; j < 8; j++) {
            float e0 = exp2f(fmaf(s[2*j][0],   Cs, nmAC));
            float e1 = exp2f(fmaf(s[2*j][1],   Cs, nmAC));
            float e2 = exp2f(fmaf(s[2*j][2],   Cs, nmBC));
            float e3 = exp2f(fmaf(s[2*j][3],   Cs, nmBC));
            float f0 = exp2f(fmaf(s[2*j+1][0], Cs, nmAC));
            float f1 = exp2f(fmaf(s[2*j+1][1], Cs, nmAC));
            float f2 = exp2f(fmaf(s[2*j+1][2], Cs, nmBC));
            float f3 = exp2f(fmaf(s[2*j+1][3], Cs, nmBC));
            sumA += e0 + e1 + f0 + f1;
            sumB += e2 + e3 + f2 + f3;
            pf[j][0] = h2u(e0, e1); pf[j][1] = h2u(e2, e3);
            pf[j][2] = h2u(f0, f1); pf[j][3] = h2u(f2, f3);
        }
        sumA += __shfl_xor_sync(0xFFFFFFFFu, sumA, 1);
        sumA += __shfl_xor_sync(0xFFFFFFFFu, sumA, 2);
        sumB += __shfl_xor_sync(0xFFFFFFFFu, sumB, 1);
        sumB += __shfl_xor_sync(0xFFFFFFFFu, sumB, 2);
        lS[0] = lS[0] * aA + sumA;
        lS[1] = lS[1] * aB + sumB;

#pragma unroll
        for (int nt = 0; nt < 16; nt++) {
            o[nt][0] *= aA; o[nt][1] *= aA; o[nt][2] *= aB; o[nt][3] *= aB;
        }

        // ---- O += P @ Vblk  (V row-major, fragments via trans ldsm) ----
#pragma unroll
        for (int j = 0; j < 8; j++) {
            uint32_t vf[8][4];
#pragma unroll
            for (int p = 0; p < 8; p++)
                ldsm4t(vf[p], curV + vOff + j * (16 * FROWB) + p * 32);
#pragma unroll
            for (int p = 0; p < 8; p++) {
                mma16816(o[2*p],   pf[j], vf[p]);
                mma16816(o[2*p+1], pf[j], vf[p] + 2);
            }
        }
        __syncthreads();
    }

    int rowA = q0 + w * 16 + (lane >> 2);
    int rowB = rowA + 8;
    float invA = (rowA == 0) ? 0.f : 1.f / lS[0];
    float invB = 1.f / lS[1];
    __half* oA = t1h + ((long)b * Ss + rowA) * Dd + h * DKk + (lane & 3) * 2;
    __half* oB = t1h + ((long)b * Ss + rowB) * Dd + h * DKk + (lane & 3) * 2;
#pragma unroll
    for (int nt = 0; nt < 16; nt++) {
        *(__half2*)(oA + nt * 8) = __floats2half2_rn(o[nt][0]*invA, o[nt][1]*invA);
        *(__half2*)(oB + nt * 8) = __floats2half2_rn(o[nt][2]*invB, o[nt][3]*invB);
    }
}

// ---------------- residual add + LayerNorm (t input fp16) -------------------
__global__ void ln_res(const float* __restrict__ x, const __half* __restrict__ t,
                       const float* __restrict__ g, const float* __restrict__ b,
                       float* __restrict__ out, __half* __restrict__ outh)
{
    __shared__ float red[256];
    long row = blockIdx.x;
    int tid = threadIdx.x;
    const float*  xp = x + row * Dd;
    const __half* tp = t + row * Dd;

    float v[4];
    float s = 0.f;
#pragma unroll
    for (int q = 0; q < 4; q++) {
        int c = tid + q * 256;
        v[q] = xp[c] + __half2float(tp[c]);
        s += v[q];
    }
    red[tid] = s; __syncthreads();
    for (int off = 128; off > 0; off >>= 1) {
        if (tid < off) red[tid] += red[tid + off];
        __syncthreads();
    }
    float mean = red[0] * (1.f / Dd);
    __syncthreads();

    float s2 = 0.f;
#pragma unroll
    for (int q = 0; q < 4; q++) {
        float d = v[q] - mean;
        s2 += d * d;
    }
    red[tid] = s2; __syncthreads();
    for (int off = 128; off > 0; off >>= 1) {
        if (tid < off) red[tid] += red[tid + off];
        __syncthreads();
    }
    float inv = rsqrtf(red[0] * (1.f / Dd) + 1e-5f);

#pragma unroll
    for (int q = 0; q < 4; q++) {
        int c = tid + q * 256;
        float val = (v[q] - mean) * inv * g[c] + b[c];
        out[row * Dd + c] = val;
        if (outh) outh[row * Dd + c] = __float2half(val);
    }
}

// ---------------- driver ----------------------------------------------------
extern "C" void kernel_launch(void* const* d_in, const int* in_sizes, int n_in,
                              void* d_out, int out_size)
{
    const float* q_embed = (const float*)d_in[0];
    const float* qa_embed= (const float*)d_in[1];
    const float* pos     = (const float*)d_in[2];
    const float* Wk  = (const float*)d_in[3];
    const float* bk  = (const float*)d_in[4];
    const float* Wv  = (const float*)d_in[5];
    const float* bv  = (const float*)d_in[6];
    const float* Wo  = (const float*)d_in[7];
    const float* bo  = (const float*)d_in[8];
    const float* ln1g= (const float*)d_in[9];
    const float* ln1b= (const float*)d_in[10];
    const float* W1  = (const float*)d_in[11];
    const float* b1  = (const float*)d_in[12];
    const float* W2  = (const float*)d_in[13];
    const float* b2  = (const float*)d_in[14];
    const float* ln2g= (const float*)d_in[15];
    const float* ln2b= (const float*)d_in[16];
    float* out = (float*)d_out;

    float *x;
    __half *t2h, *xh, *yh, *kh, *vh, *t1h, *ffh;
    __half *wk, *wv, *wo, *w1, *w2;
    cudaGetSymbolAddress((void**)&x,   g_x);
    cudaGetSymbolAddress((void**)&t2h, g_t2h);
    cudaGetSymbolAddress((void**)&xh,  g_xh);
    cudaGetSymbolAddress((void**)&yh,  g_yh);
    cudaGetSymbolAddress((void**)&kh,  g_kh);
    cudaGetSymbolAddress((void**)&vh,  g_vh);
    cudaGetSymbolAddress((void**)&t1h, g_t1h);
    cudaGetSymbolAddress((void**)&ffh, g_ffh);
    cudaGetSymbolAddress((void**)&wk,  g_wk);
    cudaGetSymbolAddress((void**)&wv,  g_wv);
    cudaGetSymbolAddress((void**)&wo,  g_wo);
    cudaGetSymbolAddress((void**)&w1,  g_w1);
    cudaGetSymbolAddress((void**)&w2,  g_w2);

    cudaFuncSetAttribute(gemm_h, cudaFuncAttributeMaxDynamicSharedMemorySize,
                         DSMEM_BYTES);
    cudaFuncSetAttribute(flash_attn, cudaFuncAttributeMaxDynamicSharedMemorySize,
                         FL_SMEM);

    add_pos_kernel<<<(Bb*Ss*Dd)/256, 256>>>(q_embed, qa_embed, pos, x, xh, yh);

    for (int l = 0; l < Ll; l++) {
        const float* bkl_ = bk + (long)l*Dd;
        const float* bvl_ = bv + (long)l*Dd;
        const float* bol_ = bo + (long)l*Dd;
        const float* b1l_ = b1 + (long)l*FFf;
        const float* b2l_ = b2 + (long)l*Dd;

        wconv_all<<<(WCONV_TOTAL + 255)/256, 256>>>(
            Wk + (long)l*Dd*Dd, Wv + (long)l*Dd*Dd, Wo + (long)l*Dd*Dd,
            W1 + (long)l*FFf*Dd, W2 + (long)l*Dd*FFf,
            wk, wv, wo, w1, w2);

        dim3 gKV(Dd/128,  (Bb*Ss)/128, 2);  // fused K+V projections
        dim3 gP (Dd/128,  (Bb*Ss)/128, 1);
        dim3 gF1(FFf/128, (Bb*Ss)/128, 1);
        dim3 gF2(Dd/128,  (Bb*Ss)/128, 1);
        dim3 gFA(Ss/128,  Bb*Hh);

        // K = x @ Wk^T + bk ; V = y @ Wv^T + bv   (one fused launch, z=0/1)
        gemm_h<<<gKV, 256, DSMEM_BYTES>>>(xh, yh, Dd, wk, wv, Dd,
                                          bkl_, bvl_, kh, vh, Dd, Dd, 0);
        // fused attention: scores + masked softmax + P@V -> t1h
        flash_attn<<<gFA, 256, FL_SMEM>>>(kh, vh, t1h);
        // t2 = t1 @ Wo^T + bo -> fp16
        gemm_h<<<gP, 256, DSMEM_BYTES>>>(t1h, nullptr, Dd, wo, nullptr, Dd,
                                         bol_, nullptr, t2h, nullptr, Dd, Dd, 0);
        // x = LN(x + t2) -> fp32 + fp16
        ln_res<<<Bb*Ss, 256>>>(x, t2h, ln1g + (long)l*Dd, ln1b + (long)l*Dd, x, xh);
        // ff = relu(x @ W1^T + b1) -> fp16
        gemm_h<<<gF1, 256, DSMEM_BYTES>>>(xh, nullptr, Dd, w1, nullptr, Dd,
                                          b1l_, nullptr, ffh, nullptr, FFf, Dd, 1);
        // t2 = ff @ W2^T + b2 -> fp16
        gemm_h<<<gF2, 256, DSMEM_BYTES>>>(ffh, nullptr, FFf, w2, nullptr, FFf,
                                          b2l_, nullptr, t2h, nullptr, Dd, FFf, 0);
        // x = LN(x + t2); final layer -> d_out (fp32 only)
        float* xout = (l == Ll - 1) ? out : x;
        __half* xhout = (l == Ll - 1) ? nullptr : xh;
        ln_res<<<Bb*Ss, 256>>>(x, t2h, ln2g + (long)l*Dd, ln2b + (long)l*Dd,
                               xout, xhout);
    }
}

// round 17
// speedup vs baseline: 1.3178x; 1.0038x over previous
#include <cuda_runtime.h>
#include <cuda_fp16.h>
#include <math.h>
#include <stdint.h>

// Problem constants
#define Bb 8
#define Ss 1024
#define Dd 1024
#define Hh 8
#define DKk 128
#define FFf 4096
#define Ll 2

// ---------------- scratch (device globals; no allocation allowed) ----------
__device__ float  g_x [Bb*Ss*Dd];                 // fp32 activation (residual)
__device__ __half g_t2h[Bb*Ss*Dd];                // fp16 branch output
__device__ __half g_xh [Bb*Ss*Dd];
__device__ __half g_yh [Bb*Ss*Dd];
__device__ __half g_kh [Bb*Ss*Dd];
__device__ __half g_vh [Bb*Ss*Dd];                // V row-major [b,s,h*dk]
__device__ __half g_t1h[Bb*Ss*Dd];
__device__ __half g_ffh[Bb*Ss*FFf];
// fp16 weights, BOTH layers pre-converted ([layer][...])
__device__ __half g_wk[Ll*Dd*Dd];
__device__ __half g_wv[Ll*Dd*Dd];
__device__ __half g_wo[Ll*Dd*Dd];
__device__ __half g_w1[Ll*FFf*Dd];
__device__ __half g_w2[Ll*Dd*FFf];

// side stream + events for off-critical-path weight conversion
static cudaStream_t g_s2;
static cudaEvent_t  g_evFork, g_evJoin;
namespace { struct StreamInit {
    StreamInit() {
        cudaStreamCreateWithFlags(&g_s2, cudaStreamNonBlocking);
        cudaEventCreateWithFlags(&g_evFork, cudaEventDisableTiming);
        cudaEventCreateWithFlags(&g_evJoin, cudaEventDisableTiming);
    }
} g_streamInit; }

// ======================= helpers ============================================
__device__ __forceinline__ uint32_t smem_u32(const void* p) {
    uint32_t a;
    asm("{ .reg .u64 t; cvta.to.shared.u64 t, %1; cvt.u32.u64 %0, t; }"
        : "=r"(a) : "l"(p));
    return a;
}

__device__ __forceinline__ void ldsm4(uint32_t* r, uint32_t addr) {
    asm volatile("ldmatrix.sync.aligned.m8n8.x4.shared.b16 {%0,%1,%2,%3}, [%4];"
        : "=r"(r[0]), "=r"(r[1]), "=r"(r[2]), "=r"(r[3]) : "r"(addr));
}

__device__ __forceinline__ void ldsm4t(uint32_t* r, uint32_t addr) {
    asm volatile("ldmatrix.sync.aligned.m8n8.x4.trans.shared.b16 {%0,%1,%2,%3}, [%4];"
        : "=r"(r[0]), "=r"(r[1]), "=r"(r[2]), "=r"(r[3]) : "r"(addr));
}

__device__ __forceinline__ void mma16816(float* c, const uint32_t* a,
                                         const uint32_t* b) {
    asm volatile(
        "mma.sync.aligned.m16n8k16.row.col.f32.f16.f16.f32 "
        "{%0,%1,%2,%3}, {%4,%5,%6,%7}, {%8,%9}, {%0,%1,%2,%3};"
        : "+f"(c[0]), "+f"(c[1]), "+f"(c[2]), "+f"(c[3])
        : "r"(a[0]), "r"(a[1]), "r"(a[2]), "r"(a[3]), "r"(b[0]), "r"(b[1]));
}

__device__ __forceinline__ void cp16(uint32_t dst, const void* src) {
    asm volatile("cp.async.cg.shared.global [%0], [%1], 16;"
        :: "r"(dst), "l"(src));
}
#define CP_COMMIT() asm volatile("cp.async.commit_group;" ::: "memory")
#define CP_WAIT(n)  asm volatile("cp.async.wait_group %0;" :: "n"(n) : "memory")

__device__ __forceinline__ uint32_t h2u(float a, float b) {
    __half2 h = __floats2half2_rn(a, b);
    return *(uint32_t*)&h;
}

// ---------------- small elementwise kernels ---------------------------------
__global__ void add_pos_kernel(const float* __restrict__ q,
                               const float* __restrict__ qa,
                               const float* __restrict__ pe,
                               float* __restrict__ x,
                               __half* __restrict__ xh,
                               __half* __restrict__ yh)
{
    int idx = blockIdx.x * 256 + threadIdx.x;
    int sd  = idx & (Ss*Dd - 1);
    float p = pe[sd];
    float xv = q[idx] + p;
    x[idx]  = xv;
    xh[idx] = __float2half(xv);
    yh[idx] = __float2half(qa[idx] + p);
}

// Convert all weight matrices for BOTH layers in one launch (runs on the side
// stream, overlapped with add_pos; joined before the first GEMM).
#define NW1 (Dd*Dd)
#define NWF (FFf*Dd)
#define WCONV_TOTAL (3*NW1 + 2*NWF)
__global__ void wconv_all(const float* __restrict__ Wk,
                          const float* __restrict__ Wv,
                          const float* __restrict__ Wo,
                          const float* __restrict__ W1,
                          const float* __restrict__ W2,
                          __half* __restrict__ wk, __half* __restrict__ wv,
                          __half* __restrict__ wo, __half* __restrict__ w1,
                          __half* __restrict__ w2)
{
    int gi = blockIdx.x * 256 + threadIdx.x;
    int l  = (gi >= WCONV_TOTAL);
    int i  = gi - l * WCONV_TOTAL;
    const float* wks = Wk + (long)l * NW1;
    const float* wvs = Wv + (long)l * NW1;
    const float* wos = Wo + (long)l * NW1;
    const float* w1s = W1 + (long)l * NWF;
    const float* w2s = W2 + (long)l * NWF;
    __half* wkd = wk + (long)l * NW1;
    __half* wvd = wv + (long)l * NW1;
    __half* wod = wo + (long)l * NW1;
    __half* w1d = w1 + (long)l * NWF;
    __half* w2d = w2 + (long)l * NWF;
    if (i < NW1)              wkd[i] = __float2half(wks[i]);
    else if (i < 2*NW1)       wvd[i - NW1]   = __float2half(wvs[i - NW1]);
    else if (i < 3*NW1)       wod[i - 2*NW1] = __float2half(wos[i - 2*NW1]);
    else if (i < 3*NW1 + NWF) w1d[i - 3*NW1] = __float2half(w1s[i - 3*NW1]);
    else                      w2d[i - 3*NW1 - NWF] = __float2half(w2s[i - 3*NW1 - NWF]);
}

// ============ fp16 GEMM: C = A * B^T (+bias)(+relu) =========================
// A: [M,K] fp16 row-major. B: [N,K] fp16 row-major. fp32 accumulate.
// CTA tile 128x128 (8 warps of 32x64), K staged 64 wide, 3-stage cp.async ring,
// one __syncthreads per stage, 2 CTAs/SM.
// blockIdx.z == 1 selects the (A2, B2, bias2, C2) operand set (fused K+V).
#define ROWB 144                    // 64 halves (128B) + 16B pad
#define ATILEB (128 * ROWB)         // 18432
#define BTILEB (128 * ROWB)         // 18432
#define STAGEB (ATILEB + BTILEB)    // 36864
#define NSTAGE 3
#define DSMEM_BYTES (NSTAGE * STAGEB)   // 110592

__device__ __forceinline__ void load_stage(
    int tid, uint32_t base,
    const __half* A, int lda, const __half* B, int ldb,
    int m0, int n0, int k0)
{
#pragma unroll
    for (int j = 0; j < 4; j++) {
        int c = tid + j * 256;              // 0..1023
        int row = c >> 3, c8 = c & 7;
        cp16(base + (uint32_t)(row * ROWB + c8 * 16),
             A + (long)(m0 + row) * lda + k0 + c8 * 8);
    }
#pragma unroll
    for (int j = 0; j < 4; j++) {
        int c = tid + j * 256;
        int row = c >> 3, c8 = c & 7;
        cp16(base + ATILEB + (uint32_t)(row * ROWB + c8 * 16),
             B + (long)(n0 + row) * ldb + k0 + c8 * 8);
    }
}

__global__ void __launch_bounds__(256, 2)
gemm_h(const __half* __restrict__ A, const __half* __restrict__ A2, int lda,
       const __half* __restrict__ B, const __half* __restrict__ B2, int ldb,
       const float* __restrict__ bias, const float* __restrict__ bias2,
       __half* __restrict__ Ch, __half* __restrict__ C2,
       int ldc, int K, int relu)
{
    extern __shared__ char dsm[];
    uint32_t sb = smem_u32(dsm);

    if (blockIdx.z) { A = A2; B = B2; bias = bias2; Ch = C2; }

    const int m0 = blockIdx.y * 128, n0 = blockIdx.x * 128;
    const int tid  = threadIdx.x;
    const int lane = tid & 31, wid = tid >> 5;
    const int mW = (wid & 3) * 32, nW = (wid >> 2) * 64;

    const uint32_t aRowOff = (uint32_t)((mW + (lane & 15)) * ROWB + (lane >> 4) * 16);
    const uint32_t bRowOff = (uint32_t)((nW + (lane & 7) + ((lane >> 4) * 8)) * ROWB
                                        + ((lane >> 3) & 1) * 16);

    const int nst = K >> 6;
    float acc[2][8][4] = {};

    load_stage(tid, sb, A, lda, B, ldb, m0, n0, 0);
    CP_COMMIT();
    if (nst > 1) load_stage(tid, sb + STAGEB, A, lda, B, ldb, m0, n0, 64);
    CP_COMMIT();

    int slot = 0;
    for (int s = 0; s < nst; s++) {
        CP_WAIT(1);
        __syncthreads();            // single barrier per stage
        uint32_t cur = sb + (uint32_t)slot * STAGEB;

        if (s + 2 < nst) {
            int nslot = slot + 2; if (nslot >= NSTAGE) nslot -= NSTAGE;
            load_stage(tid, sb + (uint32_t)nslot * STAGEB,
                       A, lda, B, ldb, m0, n0, (s + 2) * 64);
        }
        CP_COMMIT();

#pragma unroll
        for (int kk = 0; kk < 4; kk++) {
            const uint32_t kb = (uint32_t)kk * 32;
            uint32_t a[2][4], b[4][4];
#pragma unroll
            for (int mt = 0; mt < 2; mt++)
                ldsm4(a[mt], cur + aRowOff + mt * (16 * ROWB) + kb);
#pragma unroll
            for (int nh = 0; nh < 4; nh++)
                ldsm4(b[nh], cur + ATILEB + bRowOff + nh * (16 * ROWB) + kb);
#pragma unroll
            for (int nh = 0; nh < 4; nh++)
#pragma unroll
                for (int hf = 0; hf < 2; hf++)
#pragma unroll
                    for (int mt = 0; mt < 2; mt++)
                        mma16816(acc[mt][nh*2+hf], a[mt], b[nh] + 2*hf);
        }
        slot++; if (slot == NSTAGE) slot = 0;
    }

    // ---- epilogue: fp16 output ----
    const int rIn = lane >> 2, cIn = (lane & 3) * 2;
#pragma unroll
    for (int mt = 0; mt < 2; mt++) {
#pragma unroll
        for (int nt = 0; nt < 8; nt++) {
            float* a4 = acc[mt][nt];
            int col = n0 + nW + nt*8 + cIn;
            long r0 = (long)m0 + mW + mt*16 + rIn;
            long r1 = r0 + 8;
            float v0 = a4[0], v1 = a4[1], v2 = a4[2], v3 = a4[3];
            if (bias) {
                float b0_ = bias[col], b1_ = bias[col+1];
                v0 += b0_; v1 += b1_; v2 += b0_; v3 += b1_;
            }
            if (relu) {
                v0 = fmaxf(v0,0.f); v1 = fmaxf(v1,0.f);
                v2 = fmaxf(v2,0.f); v3 = fmaxf(v3,0.f);
            }
            *(__half2*)(Ch + r0*ldc + col) = __floats2half2_rn(v0, v1);
            *(__half2*)(Ch + r1*ldc + col) = __floats2half2_rn(v2, v3);
        }
    }
}

// ============ fused flash attention (strict causal, row0 zeroed) ============
// 128-row K/V blocks, 2-deep cp.async prefetch, heavy-first ordering;
// softmax in exp2 form with 1/sqrt(dk)*log2(e) folded into one fma.
#define FROWB 272
#define FTILE (128 * FROWB)                 // 34816
#define FL_SMEM (5 * FTILE)                 // Q + 2xK + 2xV = 174080

__device__ __forceinline__ void fl_load(int tid, uint32_t dstK, uint32_t dstV,
                                        const __half* Kb, const __half* Vb,
                                        int s0)
{
#pragma unroll
    for (int j = 0; j < 8; j++) {
        int c = tid + j * 256;              // 0..2047
        int row = c >> 4, cc = c & 15;
        uint32_t off = (uint32_t)(row * FROWB + cc * 16);
        cp16(dstK + off, Kb + (long)(s0 + row) * Dd + cc * 8);
        cp16(dstV + off, Vb + (long)(s0 + row) * Dd + cc * 8);
    }
}

__global__ void __launch_bounds__(256, 1)
flash_attn(const __half* __restrict__ kh, const __half* __restrict__ vh,
           __half* __restrict__ t1h)
{
    extern __shared__ char dsm[];
    uint32_t sb = smem_u32(dsm);
    uint32_t sQ = sb, sK = sb + FTILE, sV = sb + 3 * FTILE;

    // heavy-first: largest q0 (most K blocks) scheduled earliest
    const int q0 = (int)(gridDim.x - 1 - blockIdx.x) * 128;
    const int bh = blockIdx.y;
    const int b = bh >> 3, h = bh & 7;
    const __half* Kbase = kh + ((long)b * Ss) * Dd + h * DKk;
    const __half* Vbase = vh + ((long)b * Ss) * Dd + h * DKk;

    const int tid = threadIdx.x, lane = tid & 31, w = tid >> 5;
    const float Cs = 0.08838834764831845f * 1.44269504088896f; // isd*log2(e)

#pragma unroll
    for (int j = 0; j < 8; j++) {
        int c = tid + j * 256;
        int row = c >> 4, cc = c & 15;
        cp16(sQ + (uint32_t)(row * FROWB + cc * 16),
             Kbase + (long)(q0 + row) * Dd + cc * 8);
    }
    CP_COMMIT();
    fl_load(tid, sK, sV, Kbase, Vbase, 0);
    CP_COMMIT();

    CP_WAIT(1);          // Q ready
    __syncthreads();

    uint32_t qf[8][4];
    const uint32_t qAddr = sQ + (uint32_t)((w * 16 + (lane & 15)) * FROWB
                                           + (lane >> 4) * 16);
#pragma unroll
    for (int kk = 0; kk < 8; kk++) ldsm4(qf[kk], qAddr + kk * 32);

    float o[16][4] = {};
    float mS[2] = {-1e30f, -1e30f};     // running max, raw score units
    float lS[2] = {0.f, 0.f};

    const uint32_t bOff = (uint32_t)(((lane & 7) + ((lane >> 4) * 8)) * FROWB
                                     + ((lane >> 3) & 1) * 16);
    const uint32_t vOff = (uint32_t)((lane & 15) * FROWB + (lane >> 4) * 16);
    const int nkb = q0 / 128 + 1;

    for (int kb = 0; kb < nkb; kb++) {
        if (kb + 1 < nkb)
            fl_load(tid, sK + (uint32_t)((kb + 1) & 1) * FTILE,
                    sV + (uint32_t)((kb + 1) & 1) * FTILE,
                    Kbase, Vbase, (kb + 1) * 128);
        CP_COMMIT();
        CP_WAIT(1);
        __syncthreads();
        uint32_t curK = sK + (uint32_t)(kb & 1) * FTILE;
        uint32_t curV = sV + (uint32_t)(kb & 1) * FTILE;

        // ---- S = Q @ Kblk^T  (raw, unscaled) ----
        float s[16][4] = {};
#pragma unroll
        for (int kk = 0; kk < 8; kk++) {
            uint32_t bf[8][4];
#pragma unroll
            for (int p = 0; p < 8; p++)
                ldsm4(bf[p], curK + bOff + p * (16 * FROWB) + kk * 32);
#pragma unroll
            for (int p = 0; p < 8; p++) {
                mma16816(s[2*p],   qf[kk], bf[p]);
                mma16816(s[2*p+1], qf[kk], bf[p] + 2);
            }
        }

        // strict causal mask (raw-score units; mask sentinel is -1e30)
        if (kb == nkb - 1) {
            int rA = q0 + w * 16 + (lane >> 2);
            int rB = rA + 8;
            int cb = kb * 128 + (lane & 3) * 2;
#pragma unroll
            for (int nt = 0; nt < 16; nt++) {
                int c0 = cb + nt * 8, c1 = c0 + 1;
                if (c0 >= rA) s[nt][0] = -1e30f;
                if (c1 >= rA) s[nt][1] = -1e30f;
                if (c0 >= rB) s[nt][2] = -1e30f;
                if (c1 >= rB) s[nt][3] = -1e30f;
            }
        }

        // ---- online softmax (exp2 with folded scale) ----
        float rAm = -1e30f, rBm = -1e30f;
#pragma unroll
        for (int nt = 0; nt < 16; nt++) {
            rAm = fmaxf(rAm, fmaxf(s[nt][0], s[nt][1]));
            rBm = fmaxf(rBm, fmaxf(s[nt][2], s[nt][3]));
        }
        rAm = fmaxf(rAm, __shfl_xor_sync(0xFFFFFFFFu, rAm, 1));
        rAm = fmaxf(rAm, __shfl_xor_sync(0xFFFFFFFFu, rAm, 2));
        rBm = fmaxf(rBm, __shfl_xor_sync(0xFFFFFFFFu, rBm, 1));
        rBm = fmaxf(rBm, __shfl_xor_sync(0xFFFFFFFFu, rBm, 2));

        float mA = fmaxf(mS[0], rAm), mB = fmaxf(mS[1], rBm);
        float aA = exp2f((mS[0] - mA) * Cs), aB = exp2f((mS[1] - mB) * Cs);
        mS[0] = mA; mS[1] = mB;
        float nmAC = -mA * Cs, nmBC = -mB * Cs;

        float sumA = 0.f, sumB = 0.f;
        uint32_t pf[8][4];
#pragma unroll
        for (int j = 0; j < 8; j++) {
            float e0 = exp2f(fmaf(s[2*j][0],   Cs, nmAC));
            float e1 = exp2f(fmaf(s[2*j][1],   Cs, nmAC));
            float e2 = exp2f(fmaf(s[2*j][2],   Cs, nmBC));
            float e3 = exp2f(fmaf(s[2*j][3],   Cs, nmBC));
            float f0 = exp2f(fmaf(s[2*j+1][0], Cs, nmAC));
            float f1 = exp2f(fmaf(s[2*j+1][1], Cs, nmAC));
            float f2 = exp2f(fmaf(s[2*j+1][2], Cs, nmBC));
            float f3 = exp2f(fmaf(s[2*j+1][3], Cs, nmBC));
            sumA += e0 + e1 + f0 + f1;
            sumB += e2 + e3 + f2 + f3;
            pf[j][0] = h2u(e0, e1); pf[j][1] = h2u(e2, e3);
            pf[j][2] = h2u(f0, f1); pf[j][3] = h2u(f2, f3);
        }
        sumA += __shfl_xor_sync(0xFFFFFFFFu, sumA, 1);
        sumA += __shfl_xor_sync(0xFFFFFFFFu, sumA, 2);
        sumB += __shfl_xor_sync(0xFFFFFFFFu, sumB, 1);
        sumB += __shfl_xor_sync(0xFFFFFFFFu, sumB, 2);
        lS[0] = lS[0] * aA + sumA;
        lS[1] = lS[1] * aB + sumB;

#pragma unroll
        for (int nt = 0; nt < 16; nt++) {
            o[nt][0] *= aA; o[nt][1] *= aA; o[nt][2] *= aB; o[nt][3] *= aB;
        }

        // ---- O += P @ Vblk  (V row-major, fragments via trans ldsm) ----
#pragma unroll
        for (int j = 0; j < 8; j++) {
            uint32_t vf[8][4];
#pragma unroll
            for (int p = 0; p < 8; p++)
                ldsm4t(vf[p], curV + vOff + j * (16 * FROWB) + p * 32);
#pragma unroll
            for (int p = 0; p < 8; p++) {
                mma16816(o[2*p],   pf[j], vf[p]);
                mma16816(o[2*p+1], pf[j], vf[p] + 2);
            }
        }
        if (kb + 1 < nkb) __syncthreads();   // no buffer reuse after last block
    }

    int rowA = q0 + w * 16 + (lane >> 2);
    int rowB = rowA + 8;
    float invA = (rowA == 0) ? 0.f : 1.f / lS[0];
    float invB = 1.f / lS[1];
    __half* oA = t1h + ((long)b * Ss + rowA) * Dd + h * DKk + (lane & 3) * 2;
    __half* oB = t1h + ((long)b * Ss + rowB) * Dd + h * DKk + (lane & 3) * 2;
#pragma unroll
    for (int nt = 0; nt < 16; nt++) {
        *(__half2*)(oA + nt * 8) = __floats2half2_rn(o[nt][0]*invA, o[nt][1]*invA);
        *(__half2*)(oB + nt * 8) = __floats2half2_rn(o[nt][2]*invB, o[nt][3]*invB);
    }
}

// ---------------- residual add + LayerNorm (t input fp16) -------------------
__global__ void ln_res(const float* __restrict__ x, const __half* __restrict__ t,
                       const float* __restrict__ g, const float* __restrict__ b,
                       float* __restrict__ out, __half* __restrict__ outh)
{
    __shared__ float red[256];
    long row = blockIdx.x;
    int tid = threadIdx.x;
    const float*  xp = x + row * Dd;
    const __half* tp = t + row * Dd;

    float v[4];
    float s = 0.f;
#pragma unroll
    for (int q = 0; q < 4; q++) {
        int c = tid + q * 256;
        v[q] = xp[c] + __half2float(tp[c]);
        s += v[q];
    }
    red[tid] = s; __syncthreads();
    for (int off = 128; off > 0; off >>= 1) {
        if (tid < off) red[tid] += red[tid + off];
        __syncthreads();
    }
    float mean = red[0] * (1.f / Dd);
    __syncthreads();

    float s2 = 0.f;
#pragma unroll
    for (int q = 0; q < 4; q++) {
        float d = v[q] - mean;
        s2 += d * d;
    }
    red[tid] = s2; __syncthreads();
    for (int off = 128; off > 0; off >>= 1) {
        if (tid < off) red[tid] += red[tid + off];
        __syncthreads();
    }
    float inv = rsqrtf(red[0] * (1.f / Dd) + 1e-5f);

#pragma unroll
    for (int q = 0; q < 4; q++) {
        int c = tid + q * 256;
        float val = (v[q] - mean) * inv * g[c] + b[c];
        out[row * Dd + c] = val;
        if (outh) outh[row * Dd + c] = __float2half(val);
    }
}

// ---------------- driver ----------------------------------------------------
extern "C" void kernel_launch(void* const* d_in, const int* in_sizes, int n_in,
                              void* d_out, int out_size)
{
    const float* q_embed = (const float*)d_in[0];
    const float* qa_embed= (const float*)d_in[1];
    const float* pos     = (const float*)d_in[2];
    const float* Wk  = (const float*)d_in[3];
    const float* bk  = (const float*)d_in[4];
    const float* Wv  = (const float*)d_in[5];
    const float* bv  = (const float*)d_in[6];
    const float* Wo  = (const float*)d_in[7];
    const float* bo  = (const float*)d_in[8];
    const float* ln1g= (const float*)d_in[9];
    const float* ln1b= (const float*)d_in[10];
    const float* W1  = (const float*)d_in[11];
    const float* b1  = (const float*)d_in[12];
    const float* W2  = (const float*)d_in[13];
    const float* b2  = (const float*)d_in[14];
    const float* ln2g= (const float*)d_in[15];
    const float* ln2b= (const float*)d_in[16];
    float* out = (float*)d_out;

    float *x;
    __half *t2h, *xh, *yh, *kh, *vh, *t1h, *ffh;
    __half *wk, *wv, *wo, *w1, *w2;
    cudaGetSymbolAddress((void**)&x,   g_x);
    cudaGetSymbolAddress((void**)&t2h, g_t2h);
    cudaGetSymbolAddress((void**)&xh,  g_xh);
    cudaGetSymbolAddress((void**)&yh,  g_yh);
    cudaGetSymbolAddress((void**)&kh,  g_kh);
    cudaGetSymbolAddress((void**)&vh,  g_vh);
    cudaGetSymbolAddress((void**)&t1h, g_t1h);
    cudaGetSymbolAddress((void**)&ffh, g_ffh);
    cudaGetSymbolAddress((void**)&wk,  g_wk);
    cudaGetSymbolAddress((void**)&wv,  g_wv);
    cudaGetSymbolAddress((void**)&wo,  g_wo);
    cudaGetSymbolAddress((void**)&w1,  g_w1);
    cudaGetSymbolAddress((void**)&w2,  g_w2);

    cudaFuncSetAttribute(gemm_h, cudaFuncAttributeMaxDynamicSharedMemorySize,
                         DSMEM_BYTES);
    cudaFuncSetAttribute(flash_attn, cudaFuncAttributeMaxDynamicSharedMemorySize,
                         FL_SMEM);

    // Fork: convert BOTH layers' weights on the side stream, overlapping
    // with add_pos on the main stream; join before the first GEMM.
    cudaEventRecord(g_evFork, 0);
    cudaStreamWaitEvent(g_s2, g_evFork, 0);
    wconv_all<<<(2*WCONV_TOTAL + 255)/256, 256, 0, g_s2>>>(
        Wk, Wv, Wo, W1, W2, wk, wv, wo, w1, w2);
    cudaEventRecord(g_evJoin, g_s2);

    add_pos_kernel<<<(Bb*Ss*Dd)/256, 256>>>(q_embed, qa_embed, pos, x, xh, yh);

    cudaStreamWaitEvent(0, g_evJoin, 0);

    for (int l = 0; l < Ll; l++) {
        const float* bkl_ = bk + (long)l*Dd;
        const float* bvl_ = bv + (long)l*Dd;
        const float* bol_ = bo + (long)l*Dd;
        const float* b1l_ = b1 + (long)l*FFf;
        const float* b2l_ = b2 + (long)l*Dd;
        const __half* wkl = wk + (long)l*NW1;
        const __half* wvl = wv + (long)l*NW1;
        const __half* wol = wo + (long)l*NW1;
        const __half* w1l = w1 + (long)l*NWF;
        const __half* w2l = w2 + (long)l*NWF;

        dim3 gKV(Dd/128,  (Bb*Ss)/128, 2);  // fused K+V projections
        dim3 gP (Dd/128,  (Bb*Ss)/128, 1);
        dim3 gF1(FFf/128, (Bb*Ss)/128, 1);
        dim3 gF2(Dd/128,  (Bb*Ss)/128, 1);
        dim3 gFA(Ss/128,  Bb*Hh);

        // K = x @ Wk^T + bk ; V = y @ Wv^T + bv   (one fused launch, z=0/1)
        gemm_h<<<gKV, 256, DSMEM_BYTES>>>(xh, yh, Dd, wkl, wvl, Dd,
                                          bkl_, bvl_, kh, vh, Dd, Dd, 0);
        // fused attention: scores + masked softmax + P@V -> t1h
        flash_attn<<<gFA, 256, FL_SMEM>>>(kh, vh, t1h);
        // t2 = t1 @ Wo^T + bo -> fp16
        gemm_h<<<gP, 256, DSMEM_BYTES>>>(t1h, nullptr, Dd, wol, nullptr, Dd,
                                         bol_, nullptr, t2h, nullptr, Dd, Dd, 0);
        // x = LN(x + t2) -> fp32 + fp16
        ln_res<<<Bb*Ss, 256>>>(x, t2h, ln1g + (long)l*Dd, ln1b + (long)l*Dd, x, xh);
        // ff = relu(x @ W1^T + b1) -> fp16
        gemm_h<<<gF1, 256, DSMEM_BYTES>>>(xh, nullptr, Dd, w1l, nullptr, Dd,
                                          b1l_, nullptr, ffh, nullptr, FFf, Dd, 1);
        // t2 = ff @ W2^T + b2 -> fp16
        gemm_h<<<gF2, 256, DSMEM_BYTES>>>(ffh, nullptr, FFf, w2l, nullptr, FFf,
                                          b2l_, nullptr, t2h, nullptr, Dd, FFf, 0);
        // x = LN(x + t2); final layer -> d_out (fp32 only)
        float* xout = (l == Ll - 1) ? out : x;
        __half* xhout = (l == Ll - 1) ? nullptr : xh;
        ln_res<<<Bb*Ss, 256>>>(x, t2h, ln2g + (long)l*Dd, ln2b + (long)l*Dd,
                               xout, xhout);
    }
}